// round 12
// baseline (speedup 1.0000x reference)
#include <cuda_runtime.h>
#include <cstdint>

// SPDUnVectorize: x[B, L] packed upper triangle (row-major, incl. diag) ->
// out[B, n, n] symmetric. B=1024, n=256, L=n(n+1)/2=32896.
//
// R10 skeleton, but the block is split into two independent 128-thread
// groups (one batch each, own smem buffer) synced by named barriers:
// halves the straggler-coupling width of the barrier.

#define NMAT   256
#define L_IN   32896
#define BATCH  1024
#define TILE   32
#define NTROW  8
#define NTILES 36
#define PAD    33

__device__ __forceinline__ int tri_off(int r) {
    return r * NMAT - (r * (r - 1)) / 2;
}

__device__ __forceinline__ void stg256(float* p, const float* v) {
    asm volatile(
        "st.global.v8.b32 [%0], {%1, %2, %3, %4, %5, %6, %7, %8};"
        :: "l"(p),
           "r"(__float_as_uint(v[0])), "r"(__float_as_uint(v[1])),
           "r"(__float_as_uint(v[2])), "r"(__float_as_uint(v[3])),
           "r"(__float_as_uint(v[4])), "r"(__float_as_uint(v[5])),
           "r"(__float_as_uint(v[6])), "r"(__float_as_uint(v[7]))
        : "memory");
}

__global__ __launch_bounds__(256, 7)
void spd_unvec_kernel(const float* __restrict__ in, float* __restrict__ out) {
    __shared__ float s[2][TILE][PAD];

    int t = blockIdx.x;
    int ti = 0;
    int rem = NTROW;
    while (t >= rem) { t -= rem; rem--; ti++; }
    const int tj = ti + t;

    const int g      = threadIdx.x >> 7;        // group 0/1 -> batch
    const int gt     = threadIdx.x & 127;       // tid within group
    const int w      = gt >> 5;                 // warp in group 0..3
    const int lane   = gt & 31;                 // column within tile
    const int b      = blockIdx.y * 2 + g;

    const float* __restrict__ inb  = in  + (size_t)b * L_IN;
    float*       __restrict__ outb = out + (size_t)b * (NMAT * NMAT);
    float (* __restrict__ sg)[PAD] = s[g];

    // mirror-phase mapping (128 threads -> 32 rows x 4 v8-chunks)
    const int mrow = gt >> 2;                   // 0..31
    const int moc  = (gt & 3) << 3;             // 0,8,16,24

    if (ti == tj) {
        const int R = ti * TILE;
        // Load upper half (cols >= row); warp w rows w*8..w*8+7.
        #pragma unroll
        for (int k = 0; k < 8; k++) {
            const int lr = w * 8 + k;
            if (lane >= lr) {
                sg[lr][lane] = inb[tri_off(R + lr) + lane - lr];
            }
        }
        asm volatile("bar.sync %0, 128;" :: "r"(g + 1) : "memory");
        // Emit full tile: select upper/transposed, v8 store.
        float m[8];
        #pragma unroll
        for (int k = 0; k < 8; k++) {
            const int c = moc + k;
            m[k] = (c >= mrow) ? sg[mrow][c] : sg[c][mrow];
        }
        stg256(&outb[(R + mrow) * NMAT + R + moc], m);
    } else {
        // Off-diagonal tile (ti < tj). Warp w rows w*8..w*8+7.
        const int cb = tj * TILE + lane;
        float v[8];
        #pragma unroll
        for (int k = 0; k < 8; k++) {
            const int r = ti * TILE + w * 8 + k;
            v[k] = inb[tri_off(r) - r + cb];
        }
        // Upper tile: direct register stores (coalesced 128B rows) + stage.
        #pragma unroll
        for (int k = 0; k < 8; k++) {
            const int lr = w * 8 + k;
            const int r  = ti * TILE + lr;
            outb[r * NMAT + cb] = v[k];
            sg[lr][lane] = v[k];
        }
        asm volatile("bar.sync %0, 128;" :: "r"(g + 1) : "memory");
        // Mirror tile: transposed smem read, one v8 store per thread... x2.
        float m[8];
        #pragma unroll
        for (int k = 0; k < 8; k++) m[k] = sg[moc + k][mrow];
        stg256(&outb[(tj * TILE + mrow) * NMAT + ti * TILE + moc], m);

        const int mrow2 = mrow;          // second chunk set: cols +32? no --
        // 128 threads x 8 floats = 1024 = full 32x32 tile; done.
        (void)mrow2;
    }
}

extern "C" void kernel_launch(void* const* d_in, const int* in_sizes, int n_in,
                              void* d_out, int out_size) {
    const float* in = (const float*)d_in[0];
    float* out = (float*)d_out;
    dim3 grid(NTILES, BATCH / 2);
    dim3 block(256);
    spd_unvec_kernel<<<grid, block>>>(in, out);
}

// round 13
// speedup vs baseline: 1.0976x; 1.0976x over previous
#include <cuda_runtime.h>
#include <cstdint>

// SPDUnVectorize: x[B, L] packed upper triangle (row-major, incl. diag) ->
// out[B, n, n] symmetric. B=1024, n=256, L=n(n+1)/2=32896.
//
// 128-thread blocks: one 32x32 tile x 2 batches. Warp w owns rows 8w..8w+7
// -> 16 staged LDGs/thread before a 4-warp-wide __syncthreads().
// Early register-direct upper stores; v8 mirror stores.

#define NMAT   256
#define L_IN   32896
#define BATCH  1024
#define TILE   32
#define NTROW  8
#define NTILES 36
#define PAD    33

__device__ __forceinline__ int tri_off(int r) {
    return r * NMAT - (r * (r - 1)) / 2;
}

__device__ __forceinline__ void stg256(float* p, const float* v) {
    asm volatile(
        "st.global.v8.b32 [%0], {%1, %2, %3, %4, %5, %6, %7, %8};"
        :: "l"(p),
           "r"(__float_as_uint(v[0])), "r"(__float_as_uint(v[1])),
           "r"(__float_as_uint(v[2])), "r"(__float_as_uint(v[3])),
           "r"(__float_as_uint(v[4])), "r"(__float_as_uint(v[5])),
           "r"(__float_as_uint(v[6])), "r"(__float_as_uint(v[7]))
        : "memory");
}

__global__ __launch_bounds__(128, 12)
void spd_unvec_kernel(const float* __restrict__ in, float* __restrict__ out) {
    __shared__ float s0[TILE][PAD];
    __shared__ float s1[TILE][PAD];

    const int b0 = blockIdx.y * 2;
    int t = blockIdx.x;

    int ti = 0;
    int rem = NTROW;
    while (t >= rem) { t -= rem; rem--; ti++; }
    const int tj = ti + t;

    const int w    = threadIdx.x >> 5;   // warp 0..3: rows 8w..8w+7
    const int lane = threadIdx.x & 31;   // column within tile

    const float* __restrict__ in0  = in  + (size_t)b0 * L_IN;
    const float* __restrict__ in1  = in0 + L_IN;
    float*       __restrict__ out0 = out + (size_t)b0 * (NMAT * NMAT);
    float*       __restrict__ out1 = out0 + (NMAT * NMAT);

    // mirror mapping: 128 threads -> 32 rows x 4 v8-chunks (per batch)
    const int mrow = threadIdx.x >> 2;          // 0..31
    const int moc  = (threadIdx.x & 3) << 3;    // 0,8,16,24

    if (ti == tj) {
        const int R = ti * TILE;
        // Load upper half (cols >= row) for both batches.
        #pragma unroll
        for (int k = 0; k < 8; k++) {
            const int lr = w * 8 + k;
            if (lane >= lr) {
                const int idx = tri_off(R + lr) + lane - lr;
                s0[lr][lane] = in0[idx];
                s1[lr][lane] = in1[idx];
            }
        }
        __syncthreads();
        // Emit full tile: select upper/transposed, v8 stores.
        float m0[8], m1[8];
        #pragma unroll
        for (int k = 0; k < 8; k++) {
            const int c = moc + k;
            const bool up = (c >= mrow);
            m0[k] = up ? s0[mrow][c] : s0[c][mrow];
            m1[k] = up ? s1[mrow][c] : s1[c][mrow];
        }
        stg256(&out0[(R + mrow) * NMAT + R + moc], m0);
        stg256(&out1[(R + mrow) * NMAT + R + moc], m1);
    } else {
        // Off-diagonal tile (ti < tj): stage 16 loads, then stores.
        const int cb = tj * TILE + lane;
        float v0[8], v1[8];
        #pragma unroll
        for (int k = 0; k < 8; k++) {
            const int r   = ti * TILE + w * 8 + k;
            const int idx = tri_off(r) - r + cb;
            v0[k] = in0[idx];
            v1[k] = in1[idx];
        }
        // Upper tile: direct register stores (coalesced 128B rows) + stage.
        #pragma unroll
        for (int k = 0; k < 8; k++) {
            const int lr = w * 8 + k;
            const int r  = ti * TILE + lr;
            out0[r * NMAT + cb] = v0[k];
            out1[r * NMAT + cb] = v1[k];
            s0[lr][lane] = v0[k];
            s1[lr][lane] = v1[k];
        }
        __syncthreads();
        // Mirror tiles: transposed smem reads, one v8 store per batch.
        float m0[8], m1[8];
        #pragma unroll
        for (int k = 0; k < 8; k++) {
            m0[k] = s0[moc + k][mrow];
            m1[k] = s1[moc + k][mrow];
        }
        stg256(&out0[(tj * TILE + mrow) * NMAT + ti * TILE + moc], m0);
        stg256(&out1[(tj * TILE + mrow) * NMAT + ti * TILE + moc], m1);
    }
}

extern "C" void kernel_launch(void* const* d_in, const int* in_sizes, int n_in,
                              void* d_out, int out_size) {
    const float* in = (const float*)d_in[0];
    float* out = (float*)d_out;
    dim3 grid(NTILES, BATCH / 2);
    dim3 block(128);
    spd_unvec_kernel<<<grid, block>>>(in, out);
}